// round 1
// baseline (speedup 1.0000x reference)
#include <cuda_runtime.h>
#include <cstdint>

#define NU 50000
#define NI 25000
#define DIMV 128
#define GROWS 8

// ------------------------- device scratch (no allocs) -------------------------
__device__ __align__(16) float g_gate[4][NU * DIMV];   // gated user embeddings (c=0..3)
__device__ __align__(16) float g_curA[3][NU * DIMV];   // layer-1 H-spmm outputs
__device__ __align__(16) float g_curB[3][NU * DIMV];   // layer-2 H-spmm outputs
__device__ __align__(16) float g_accc[3][NU * DIMV];   // sum of l2norms per channel
__device__ __align__(16) float g_mixed[NU * DIMV];
__device__ __align__(16) float g_s1[NU * DIMV];
__device__ __align__(16) float g_s2[NU * DIMV];
__device__ __align__(16) float g_sacc[NU * DIMV];      // sum l2n(cur_s layers)
__device__ __align__(16) float g_i1[NI * DIMV];
__device__ __align__(16) float g_i2[NI * DIMV];
__device__ __align__(16) float g_iacc[NI * DIMV];      // sum l2n(item layers)
__device__ float g_attvec[DIMV];

// ------------------------- attention vector: v = M @ a -------------------------
__global__ void attvec_kernel(const float* __restrict__ att, const float* __restrict__ mat) {
    int j = threadIdx.x;
    float s = 0.f;
#pragma unroll 8
    for (int d = 0; d < DIMV; d++) s += mat[j * DIMV + d] * att[d];
    g_attvec[j] = s;
}

// ------------------------- gating: G_c = U * sigmoid(U @ W_c + b_c) -------------------------
// blockIdx.y = channel. Register-blocked 8 rows per thread, W transposed in shared
// with pad 132 (stride%32==4 but LDS.128 quarter-warp phases stay conflict-free).
__global__ void __launch_bounds__(128) gate_kernel(const float* __restrict__ U,
                                                   const float* __restrict__ W4,
                                                   const float* __restrict__ B4) {
    extern __shared__ float sm[];
    float* Wt = sm;              // [128][132]  Wt[t][k] = W[k][t]
    float* Us = sm + DIMV * 132; // [8][128]
    int t = threadIdx.x;
    int c = blockIdx.y;
    const float* W = W4 + c * DIMV * DIMV;
    float b = B4[c * DIMV + t];
    float* out = g_gate[c];

    for (int k = 0; k < DIMV; k++) Wt[t * 132 + k] = W[k * DIMV + t];

    for (int r0 = blockIdx.x * GROWS; r0 < NU; r0 += gridDim.x * GROWS) {
        __syncthreads();
#pragma unroll
        for (int r = 0; r < GROWS; r++) Us[r * DIMV + t] = U[(size_t)(r0 + r) * DIMV + t];
        __syncthreads();
        float acc[GROWS];
#pragma unroll
        for (int r = 0; r < GROWS; r++) acc[r] = b;
#pragma unroll 4
        for (int k = 0; k < DIMV; k += 4) {
            float4 w = *(const float4*)&Wt[t * 132 + k];
#pragma unroll
            for (int r = 0; r < GROWS; r++) {
                float4 u = *(const float4*)&Us[r * DIMV + k];
                acc[r] += u.x * w.x;
                acc[r] += u.y * w.y;
                acc[r] += u.z * w.z;
                acc[r] += u.w * w.w;
            }
        }
#pragma unroll
        for (int r = 0; r < GROWS; r++) {
            float uv = Us[r * DIMV + t];
            float g = uv / (1.f + expf(-acc[r]));
            out[(size_t)(r0 + r) * DIMV + t] = g;
        }
    }
}

// ------------------------- COO SpMM: Y[row] += val * X[col], warp per edge -------------------------
__device__ __forceinline__ void red_add_v4(float* p, float a, float b, float c, float d) {
    asm volatile("red.global.add.v4.f32 [%0], {%1, %2, %3, %4};"
                 :: "l"(p), "f"(a), "f"(b), "f"(c), "f"(d) : "memory");
}

__global__ void __launch_bounds__(256) spmm_kernel(const int* __restrict__ rows,
                                                   const int* __restrict__ cols,
                                                   const float* __restrict__ vals,
                                                   const float* __restrict__ X,
                                                   float* __restrict__ Y, int ne) {
    int w = (int)((blockIdx.x * (unsigned)blockDim.x + threadIdx.x) >> 5);
    int lane = threadIdx.x & 31;
    if (w >= ne) return;
    int r = __ldg(rows + w);
    int c = __ldg(cols + w);
    float v = __ldg(vals + w);
    float4 x = __ldg((const float4*)(X + (size_t)c * DIMV) + lane);
    red_add_v4(Y + (size_t)r * DIMV + lane * 4, v * x.x, v * x.y, v * x.z, v * x.w);
}

// ------------------------- acc += l2norm(src), warp per row -------------------------
__global__ void __launch_bounds__(256) l2acc_kernel(const float* __restrict__ src,
                                                    float* __restrict__ acc, int nrows) {
    int w = (int)((blockIdx.x * (unsigned)blockDim.x + threadIdx.x) >> 5);
    int lane = threadIdx.x & 31;
    if (w >= nrows) return;
    size_t base = (size_t)w * DIMV + lane * 4;
    float4 x = *(const float4*)(src + base);
    float ss = x.x * x.x + x.y * x.y + x.z * x.z + x.w * x.w;
#pragma unroll
    for (int o = 16; o; o >>= 1) ss += __shfl_xor_sync(0xffffffffu, ss, o);
    float sc = rsqrtf(fmaxf(ss, 1e-12f));
    float4 a = *(const float4*)(acc + base);
    a.x += x.x * sc; a.y += x.y * sc; a.z += x.z * sc; a.w += x.w * sc;
    *(float4*)(acc + base) = a;
}

// ------------------------- channel attention mix -------------------------
// out = softmax_k(C_k·v) weighted sum of C_k + 0.5*(S [+ S2]); C_k optionally += A_k.
__global__ void __launch_bounds__(256) mix_kernel(
        const float* __restrict__ C0, const float* __restrict__ C1, const float* __restrict__ C2,
        const float* __restrict__ A0, const float* __restrict__ A1, const float* __restrict__ A2,
        const float* __restrict__ S, const float* __restrict__ S2,
        float* __restrict__ out, int nrows) {
    int w = (int)((blockIdx.x * (unsigned)blockDim.x + threadIdx.x) >> 5);
    int lane = threadIdx.x & 31;
    if (w >= nrows) return;
    size_t base = (size_t)w * DIMV + lane * 4;
    float4 v = *(const float4*)(g_attvec + lane * 4);
    float4 c0 = *(const float4*)(C0 + base);
    float4 c1 = *(const float4*)(C1 + base);
    float4 c2 = *(const float4*)(C2 + base);
    if (A0) {
        float4 a0 = *(const float4*)(A0 + base);
        float4 a1 = *(const float4*)(A1 + base);
        float4 a2 = *(const float4*)(A2 + base);
        c0.x += a0.x; c0.y += a0.y; c0.z += a0.z; c0.w += a0.w;
        c1.x += a1.x; c1.y += a1.y; c1.z += a1.z; c1.w += a1.w;
        c2.x += a2.x; c2.y += a2.y; c2.z += a2.z; c2.w += a2.w;
    }
    float w0 = c0.x * v.x + c0.y * v.y + c0.z * v.z + c0.w * v.w;
    float w1 = c1.x * v.x + c1.y * v.y + c1.z * v.z + c1.w * v.w;
    float w2 = c2.x * v.x + c2.y * v.y + c2.z * v.z + c2.w * v.w;
#pragma unroll
    for (int o = 16; o; o >>= 1) {
        w0 += __shfl_xor_sync(0xffffffffu, w0, o);
        w1 += __shfl_xor_sync(0xffffffffu, w1, o);
        w2 += __shfl_xor_sync(0xffffffffu, w2, o);
    }
    float m = fmaxf(w0, fmaxf(w1, w2));
    float e0 = expf(w0 - m), e1 = expf(w1 - m), e2 = expf(w2 - m);
    float inv = 1.f / (e0 + e1 + e2);
    e0 *= inv; e1 *= inv; e2 *= inv;
    float4 s = *(const float4*)(S + base);
    if (S2) {
        float4 s2 = *(const float4*)(S2 + base);
        s.x += s2.x; s.y += s2.y; s.z += s2.z; s.w += s2.w;
    }
    float4 o;
    o.x = e0 * c0.x + e1 * c1.x + e2 * c2.x + 0.5f * s.x;
    o.y = e0 * c0.y + e1 * c1.y + e2 * c2.y + 0.5f * s.y;
    o.z = e0 * c0.z + e1 * c1.z + e2 * c2.z + 0.5f * s.z;
    o.w = e0 * c0.w + e1 * c1.w + e2 * c2.w + 0.5f * s.w;
    *(float4*)(out + base) = o;
}

// ------------------------- item output: out = i_emb + iacc -------------------------
__global__ void __launch_bounds__(256) item_out_kernel(const float* __restrict__ ie,
                                                       const float* __restrict__ ia,
                                                       float* __restrict__ out) {
    int i = blockIdx.x * blockDim.x + threadIdx.x;
    if (i < NI * DIMV / 4) {
        float4 a = __ldg((const float4*)ie + i);
        float4 b = *((const float4*)ia + i);
        a.x += b.x; a.y += b.y; a.z += b.z; a.w += b.w;
        *((float4*)out + i) = a;
    }
}

// ------------------------- host orchestration -------------------------
extern "C" void kernel_launch(void* const* d_in, const int* in_sizes, int n_in,
                              void* d_out, int out_size) {
    const float* u_emb = (const float*)d_in[0];
    const float* i_emb = (const float*)d_in[1];
    const float* gW = (const float*)d_in[2];
    const float* gB = (const float*)d_in[3];
    const float* att = (const float*)d_in[4];
    const float* attm = (const float*)d_in[5];
    const int* Hr[3] = {(const int*)d_in[6], (const int*)d_in[9], (const int*)d_in[12]};
    const int* Hc[3] = {(const int*)d_in[7], (const int*)d_in[10], (const int*)d_in[13]};
    const float* Hv[3] = {(const float*)d_in[8], (const float*)d_in[11], (const float*)d_in[14]};
    const int* Rr = (const int*)d_in[15];
    const int* Rc = (const int*)d_in[16];
    const float* Rv = (const float*)d_in[17];
    int EH = in_sizes[6], ER = in_sizes[15];
    float* out = (float*)d_out;

    float *p_gate, *p_curA, *p_curB, *p_accc, *p_mixed, *p_s1, *p_s2, *p_sacc, *p_i1, *p_i2, *p_iacc;
    cudaGetSymbolAddress((void**)&p_gate, g_gate);
    cudaGetSymbolAddress((void**)&p_curA, g_curA);
    cudaGetSymbolAddress((void**)&p_curB, g_curB);
    cudaGetSymbolAddress((void**)&p_accc, g_accc);
    cudaGetSymbolAddress((void**)&p_mixed, g_mixed);
    cudaGetSymbolAddress((void**)&p_s1, g_s1);
    cudaGetSymbolAddress((void**)&p_s2, g_s2);
    cudaGetSymbolAddress((void**)&p_sacc, g_sacc);
    cudaGetSymbolAddress((void**)&p_i1, g_i1);
    cudaGetSymbolAddress((void**)&p_i2, g_i2);
    cudaGetSymbolAddress((void**)&p_iacc, g_iacc);

#define GP(c) (p_gate + (size_t)(c) * NU * DIMV)
#define CA(c) (p_curA + (size_t)(c) * NU * DIMV)
#define CB(c) (p_curB + (size_t)(c) * NU * DIMV)
#define AC(c) (p_accc + (size_t)(c) * NU * DIMV)

    size_t smem = (size_t)(DIMV * 132 + GROWS * DIMV) * sizeof(float);
    cudaFuncSetAttribute(gate_kernel, cudaFuncAttributeMaxDynamicSharedMemorySize, (int)smem);

    const size_t UB = (size_t)NU * DIMV * sizeof(float);
    const size_t IB = (size_t)NI * DIMV * sizeof(float);

    // zero accumulators
    cudaMemsetAsync(p_accc, 0, 3 * UB);
    cudaMemsetAsync(p_sacc, 0, UB);
    cudaMemsetAsync(p_iacc, 0, IB);

    attvec_kernel<<<1, 128>>>(att, attm);
    gate_kernel<<<dim3(448, 4), 128, smem>>>(u_emb, gW, gB);

    int mixb = (NU + 7) / 8;        // warp per row, 8 warps/block
    int l2u = (NU + 7) / 8, l2i = (NI + 7) / 8;
    int spH = (EH + 7) / 8, spR = (ER + 7) / 8;

    // ---------------- layer 1 ----------------
    mix_kernel<<<mixb, 256>>>(GP(0), GP(1), GP(2), nullptr, nullptr, nullptr,
                              GP(3), nullptr, p_mixed, NU);
    cudaMemsetAsync(p_curA, 0, 3 * UB);
    cudaMemsetAsync(p_i1, 0, IB);
    cudaMemsetAsync(p_s1, 0, UB);
    for (int k = 0; k < 3; k++)
        spmm_kernel<<<spH, 256>>>(Hr[k], Hc[k], Hv[k], GP(k), CA(k), EH);
    spmm_kernel<<<spR, 256>>>(Rc, Rr, Rv, p_mixed, p_i1, ER);   // new_item = R^T @ mixed
    spmm_kernel<<<spR, 256>>>(Rr, Rc, Rv, i_emb, p_s1, ER);     // cur_s = R @ i_emb
    for (int k = 0; k < 3; k++) l2acc_kernel<<<l2u, 256>>>(CA(k), AC(k), NU);
    l2acc_kernel<<<l2i, 256>>>(p_i1, p_iacc, NI);
    l2acc_kernel<<<l2u, 256>>>(p_s1, p_sacc, NU);

    // ---------------- layer 2 ----------------
    mix_kernel<<<mixb, 256>>>(CA(0), CA(1), CA(2), nullptr, nullptr, nullptr,
                              p_s1, nullptr, p_mixed, NU);
    cudaMemsetAsync(p_curB, 0, 3 * UB);
    cudaMemsetAsync(p_i2, 0, IB);
    cudaMemsetAsync(p_s2, 0, UB);
    for (int k = 0; k < 3; k++)
        spmm_kernel<<<spH, 256>>>(Hr[k], Hc[k], Hv[k], CA(k), CB(k), EH);
    spmm_kernel<<<spR, 256>>>(Rc, Rr, Rv, p_mixed, p_i2, ER);   // new_item2 = R^T @ mixed2
    spmm_kernel<<<spR, 256>>>(Rr, Rc, Rv, p_i1, p_s2, ER);      // cur_s2 = R @ item1
    for (int k = 0; k < 3; k++) l2acc_kernel<<<l2u, 256>>>(CB(k), AC(k), NU);
    l2acc_kernel<<<l2i, 256>>>(p_i2, p_iacc, NI);
    l2acc_kernel<<<l2u, 256>>>(p_s2, p_sacc, NU);

    // ---------------- final ----------------
    // final_user = chan_att(gate_k + accc_k) + 0.5*(gate3 + sacc)
    mix_kernel<<<mixb, 256>>>(GP(0), GP(1), GP(2), AC(0), AC(1), AC(2),
                              GP(3), p_sacc, out, NU);
    // final_item = i_emb + iacc
    item_out_kernel<<<(NI * DIMV / 4 + 255) / 256, 256>>>(i_emb, p_iacc,
                                                          out + (size_t)NU * DIMV);
}